// round 17
// baseline (speedup 1.0000x reference)
#include <cuda_runtime.h>
#include <stdint.h>

// Problem shape (fixed by the dataset)
#define NH 32
#define NL 8192
#define ND 128
#define NROWS (NH * NL)            // 262144
#define NKV   ((size_t)NROWS * ND) // 33554432
#define NBLK  (NROWS / 8)          // 32768 blocks, 1024 candidates per head

// Output layout: flattened concatenation of the reference tuple, fp32
static const size_t OFF_K   = 0;
static const size_t OFF_V   = NKV;
static const size_t OFF_NUM = 2 * NKV;
static const size_t OFF_POS = OFF_NUM + NH;
static const size_t OFF_KQ  = OFF_POS + NROWS;
static const size_t OFF_KSC = OFF_KQ + NKV;
static const size_t OFF_KZ  = OFF_KSC + NROWS;
static const size_t OFF_VQ  = OFF_KZ + NROWS;
static const size_t OFF_VSC = OFF_VQ + NKV;
static const size_t OFF_VZ  = OFF_VSC + NROWS;

// Per-block argmin candidates, rewritten fully on every replay.
static __device__ unsigned long long g_blockmin[NBLK];
// Completion ticket counter; last block performs fixup and resets it to 0.
static __device__ unsigned int g_ctr;

__device__ __forceinline__ unsigned int fkey(float f) {
    unsigned int u = __float_as_uint(f);
    return (u & 0x80000000u) ? ~u : (u | 0x80000000u);
}
__device__ __forceinline__ float unfkey(unsigned int k) {
    return (k & 0x80000000u) ? __uint_as_float(k & 0x7FFFFFFFu)
                             : __uint_as_float(~k);
}
__device__ __forceinline__ unsigned long long u64min(unsigned long long a,
                                                     unsigned long long b) {
    return a < b ? a : b;
}

// Fill one evicted row (K or V) with the new token and requantize it.
__device__ __forceinline__ void fill_row(
    const float4* __restrict__ src4, float* __restrict__ out,
    size_t off_deq, size_t off_q, size_t off_sc, size_t off_z,
    unsigned int row, int lane)
{
    const unsigned int rbase = row * 32u + lane;
    float4 x = src4[lane];
    float mn4 = fminf(fminf(x.x, x.y), fminf(x.z, x.w));
    float mx4 = fmaxf(fmaxf(x.x, x.y), fmaxf(x.z, x.w));
    float mn = unfkey(__reduce_min_sync(0xffffffffu, fkey(mn4)));
    float mx = unfkey(__reduce_max_sync(0xffffffffu, fkey(mx4)));
    ((float4*)(out + off_deq))[rbase] = x;
    float snew = fmaxf(__fdiv_rn(mx - mn, 15.0f), 1e-6f);
    float inv  = __fdividef(1.0f, snew);
    float off  = -mn * inv;
    float q0 = rintf(__fmaf_rn(x.x, inv, off));
    float q1 = rintf(__fmaf_rn(x.y, inv, off));
    float q2 = rintf(__fmaf_rn(x.z, inv, off));
    float q3 = rintf(__fmaf_rn(x.w, inv, off));
    ((float4*)(out + off_q))[rbase] = make_float4(q0, q1, q2, q3);
    if (lane == 0) { out[off_sc + row] = snew; out[off_z + row] = mn; }
}

// One warp per (h,l) row; 256 threads = 8 rows/block; 1024 blocks per head.
// min-8-blocks/SM launch bound caps regs at 32 -> full occupancy.
__global__ void __launch_bounds__(256, 8) pass1_kernel(
    const int4*  __restrict__ kq,
    const int4*  __restrict__ vq,
    const float* __restrict__ ksc, const float* __restrict__ kz,
    const float* __restrict__ vsc, const float* __restrict__ vz,
    const int*   __restrict__ pos,
    const float* __restrict__ w,
    const float* __restrict__ k_val,
    const float* __restrict__ v_val,
    const int*   __restrict__ input_pos_ptr,
    int input_pos_const,
    float* __restrict__ out)
{
    __shared__ unsigned long long blkmin[8];
    __shared__ unsigned int s_ticket;
    const int warp = threadIdx.x >> 5;
    const int lane = threadIdx.x & 31;
    const unsigned int row = blockIdx.x * 8u + warp;
    const int hb = blockIdx.x >> 10;      // head (constant per block)
    const int l  = row & (NL - 1);

    const unsigned int rbase = row * 32u + lane;   // 32-bit stream index

    // ---- issue ALL loads up front (MLP); w comes from L1 (same line for
    //      every warp of the block) ----
    const int4 kq4 = __ldcs(&kq[rbase]);
    const int4 vq4 = __ldcs(&vq[rbase]);
    const float4 wl = ((const float4*)(w + hb * ND))[lane];
    const float ks_ = ksc[row], kz_ = kz[row];
    const float vs_ = vsc[row], vz_ = vz[row];
    const int   p   = pos[row];

    // ---- dequant: single-rounded FFMA (<=1ulp vs unfused; quotients sit at
    //      integers so downstream rintf results are unchanged) ----
    float k0 = __fmaf_rn((float)kq4.x, ks_, kz_);
    float k1 = __fmaf_rn((float)kq4.y, ks_, kz_);
    float k2 = __fmaf_rn((float)kq4.z, ks_, kz_);
    float k3 = __fmaf_rn((float)kq4.w, ks_, kz_);
    float v0 = __fmaf_rn((float)vq4.x, vs_, vz_);
    float v1 = __fmaf_rn((float)vq4.y, vs_, vz_);
    float v2 = __fmaf_rn((float)vq4.z, vs_, vz_);
    float v3 = __fmaf_rn((float)vq4.w, vs_, vz_);

    // ---- in-thread float min/max trees, one key conversion per quantity,
    //      then single-instruction warp redux ----
    float kmn4 = fminf(fminf(k0, k1), fminf(k2, k3));
    float kmx4 = fmaxf(fmaxf(k0, k1), fmaxf(k2, k3));
    float vmn4 = fminf(fminf(v0, v1), fminf(v2, v3));
    float vmx4 = fmaxf(fmaxf(v0, v1), fmaxf(v2, v3));
    const float kmn = unfkey(__reduce_min_sync(0xffffffffu, fkey(kmn4)));
    const float kmx = unfkey(__reduce_max_sync(0xffffffffu, fkey(kmx4)));
    const float vmn = unfkey(__reduce_min_sync(0xffffffffu, fkey(vmn4)));
    const float vmx = unfkey(__reduce_max_sync(0xffffffffu, fkey(vmx4)));

    float sc = __fmaf_rn(k3, wl.w,
               __fmaf_rn(k2, wl.z,
               __fmaf_rn(k1, wl.y, k0 * wl.x)));
    #pragma unroll
    for (int o = 16; o; o >>= 1)
        sc += __shfl_xor_sync(0xffffffffu, sc, o);

    // ---- dequant outputs (streaming stores) ----
    __stcs((float4*)(out + OFF_K) + rbase, make_float4(k0, k1, k2, k3));
    __stcs((float4*)(out + OFF_V) + rbase, make_float4(v0, v1, v2, v3));

    // ---- requantize: q = rint(fma(x, inv, -mn*inv)). Warp-uniform off; the
    //      cancellation error is bounded by ulp(|mn|*inv) << the 0.5 rintf
    //      margin for near-integer quotients. snew output stays __fdiv_rn. ----
    {
        float snew = fmaxf(__fdiv_rn(kmx - kmn, 15.0f), 1e-6f);
        float inv  = __fdividef(1.0f, snew);
        float off  = -kmn * inv;
        float q0 = rintf(__fmaf_rn(k0, inv, off));
        float q1 = rintf(__fmaf_rn(k1, inv, off));
        float q2 = rintf(__fmaf_rn(k2, inv, off));
        float q3 = rintf(__fmaf_rn(k3, inv, off));
        __stcs((float4*)(out + OFF_KQ) + rbase, make_float4(q0, q1, q2, q3));
        if (lane == 0) {
            out[OFF_KSC + row] = snew;
            out[OFF_KZ + row]  = kmn;
            out[OFF_POS + row] = (float)p;
        }
    }
    {
        float snew = fmaxf(__fdiv_rn(vmx - vmn, 15.0f), 1e-6f);
        float inv  = __fdividef(1.0f, snew);
        float off  = -vmn * inv;
        float q0 = rintf(__fmaf_rn(v0, inv, off));
        float q1 = rintf(__fmaf_rn(v1, inv, off));
        float q2 = rintf(__fmaf_rn(v2, inv, off));
        float q3 = rintf(__fmaf_rn(v3, inv, off));
        __stcs((float4*)(out + OFF_VQ) + rbase, make_float4(q0, q1, q2, q3));
        if (lane == 0) {
            out[OFF_VSC + row] = snew;
            out[OFF_VZ + row]  = vmn;
        }
    }

    // ---- eviction score -> per-block min candidate ----
    float score = sc;
    if (l < 4)   score = __int_as_float(0x7F800000);   // +inf (protected)
    if (p == -1) score = __int_as_float(0xFF800000);   // -inf (empty slot)
    unsigned long long packed =
        ((unsigned long long)fkey(score) << 32) | (unsigned int)l;
    if (lane == 0) blkmin[warp] = packed;
    __syncthreads();
    if (threadIdx.x == 0) {
        unsigned long long m = blkmin[0];
        #pragma unroll
        for (int i = 1; i < 8; i++) m = u64min(m, blkmin[i]);
        g_blockmin[blockIdx.x] = m;
        __threadfence();                       // release
        s_ticket = atomicAdd(&g_ctr, 1u);
    }
    __syncthreads();

    // ---- last block: per-head argmin reduction + evict/fill ----
    if (s_ticket != NBLK - 1) return;
    __threadfence();                           // acquire
    if (threadIdx.x == 0) g_ctr = 0;           // reset for next graph replay

    const int ip = input_pos_ptr ? *input_pos_ptr : input_pos_const;
    #pragma unroll
    for (int it = 0; it < 4; ++it) {
        const int h = warp + it * 8;
        const unsigned long long* base = &g_blockmin[h * 1024];
        unsigned long long m = 0xFFFFFFFFFFFFFFFFull;
        #pragma unroll
        for (int j = 0; j < 32; ++j)
            m = u64min(m, base[lane + 32 * j]);
        #pragma unroll
        for (int o = 16; o; o >>= 1)
            m = u64min(m, __shfl_xor_sync(0xffffffffu, m, o));
        const unsigned int idx = (unsigned int)(m & 0xFFFFFFFFull);
        const unsigned int erow = (unsigned int)h * NL + idx;

        if (lane == 0) {
            out[OFF_NUM + h]    = (pos[erow] == -1) ? 1.0f : 0.0f;
            out[OFF_POS + erow] = (float)ip;
        }
        fill_row((const float4*)k_val + h * 32, out,
                 OFF_K, OFF_KQ, OFF_KSC, OFF_KZ, erow, lane);
        fill_row((const float4*)v_val + h * 32, out,
                 OFF_V, OFF_VQ, OFF_VSC, OFF_VZ, erow, lane);
    }
}

extern "C" void kernel_launch(void* const* d_in, const int* in_sizes, int n_in,
                              void* d_out, int out_size)
{
    const int4*  kq  = (const int4*)d_in[0];
    const int4*  vq  = (const int4*)d_in[1];
    const float* ksc = (const float*)d_in[2];
    const float* kz  = (const float*)d_in[3];
    const float* vsc = (const float*)d_in[4];
    const float* vz  = (const float*)d_in[5];
    const int*   pos = (const int*)d_in[6];

    const int* input_pos_ptr = nullptr;
    const float *k_val, *v_val, *w;
    if (n_in >= 11) {
        input_pos_ptr = (const int*)d_in[7];
        k_val = (const float*)d_in[8];
        v_val = (const float*)d_in[9];
        w     = (const float*)d_in[10];
    } else {
        k_val = (const float*)d_in[7];
        v_val = (const float*)d_in[8];
        w     = (const float*)d_in[9];
    }
    float* out = (float*)d_out;

    pass1_kernel<<<NBLK, 256>>>(kq, vq, ksc, kz, vsc, vz, pos, w,
                                k_val, v_val, input_pos_ptr, 8192, out);
}